// round 5
// baseline (speedup 1.0000x reference)
#include <cuda_runtime.h>
#include <cuda_fp16.h>
#include <stdint.h>

#define RES 512
#define CH 32
#define PAIR_HALVES 64   // one pair entry = 2 texels * 32 half = 128 B
#define PLANE_PAIR_ELEMS (RES * RES * PAIR_HALVES)

// Pair-duplicated planes: P[p][y*RES+x] = [texel(y,x) (32 half) | texel(y,x+1) (32 half)]
// Entry is 128B and 128B-aligned. Column x+1==RES is zero-filled.
__device__ __align__(128) __half g_P[3][PLANE_PAIR_ELEMS];

// ---------------------------------------------------------------------------
// Prep: (C,H,W) fp32 -> pair-duplicated (H,W,2,C) fp16.
// grid = (RES, RES/32, 3), block = (32, 8).
// ---------------------------------------------------------------------------
__global__ __launch_bounds__(256) void triplane_prep_kernel(
    const float* __restrict__ t_xy,
    const float* __restrict__ t_yz,
    const float* __restrict__ t_zx)
{
    __shared__ float tile[32][33];   // [channel][x-in-tile]

    const int y  = blockIdx.x;
    const int x0 = blockIdx.y * 32;
    const int p  = blockIdx.z;
    const int tx = threadIdx.x;      // 0..31
    const int ty = threadIdx.y;      // 0..7

    const float* src = (p == 0) ? t_xy : (p == 1) ? t_yz : t_zx;
    const float* s = src + y * RES + x0 + tx;

#pragma unroll
    for (int i = 0; i < 4; ++i) {
        const int c = ty + 8 * i;
        tile[c][tx] = s[c * (RES * RES)];   // coalesced, MLP=4
    }
    __syncthreads();

    const int tid = ty * 32 + tx;
    if (tid < 128) {
        const int xx  = tid >> 2;        // texel within tile (0..31)
        const int seg = tid & 3;         // which 16B segment of the 64B texel

        uint4 v;
#pragma unroll
        for (int j = 0; j < 4; ++j) {
            const int c = seg * 8 + 2 * j;
            ((__half2*)&v)[j] = __floats2half2_rn(tile[c][xx], tile[c + 1][xx]);
        }

        const int x = x0 + xx;
        __half* row = g_P[p] + (size_t)(y * RES) * PAIR_HALVES;

        // first half of entry x  (texel x)
        *(uint4*)(row + (size_t)x * PAIR_HALVES + seg * 8) = v;
        // second half of entry x-1 (texel x as the "x+1" slot)
        if (x > 0)
            *(uint4*)(row + (size_t)(x - 1) * PAIR_HALVES + 32 + seg * 8) = v;
        // zero-fill the phantom x+1 == RES column
        if (x == RES - 1)
            *(uint4*)(row + (size_t)x * PAIR_HALVES + 32 + seg * 8) =
                make_uint4(0u, 0u, 0u, 0u);
    }
}

// ---------------------------------------------------------------------------
// Sampling: 8 lanes per point. Lane s: xsel = s>>2 (x0/x1 corner),
// chunk = s&3 (8 channels). One warp LDG.128 per (plane,row) per point
// = exactly one 128B line -> 6 L1 wavefronts per point.
// ---------------------------------------------------------------------------
__global__ __launch_bounds__(256) void triplane_sample_kernel(
    const float* __restrict__ xyz,
    float* __restrict__ out,
    int npts)
{
    const int gtid  = blockIdx.x * blockDim.x + threadIdx.x;
    const int pid   = gtid >> 3;
    const int s     = gtid & 7;
    const int chunk = s & 3;
    const int xsel  = s >> 2;
    if (pid >= npts) return;

    const float cx = __ldg(xyz + pid * 3 + 0);
    const float cy = __ldg(xyz + pid * 3 + 1);
    const float cz = __ldg(xyz + pid * 3 + 2);

    // f_xy: (X, Y)   f_yz: (Y, Z)   f_zx: (Z, X)
    const float cA[3] = {cx, cy, cz};   // W coordinate
    const float cB[3] = {cy, cz, cx};   // H coordinate

    float acc[8];
#pragma unroll
    for (int j = 0; j < 8; ++j) acc[j] = 0.f;

#pragma unroll
    for (int p = 0; p < 3; ++p) {
        // pixel coord = 256*c + 255.5
        const float xf = fmaf(cA[p], 256.0f, 255.5f);
        const float yf = fmaf(cB[p], 256.0f, 255.5f);

        const float x0f = floorf(xf);
        const float y0f = floorf(yf);
        const float wx1 = xf - x0f;
        const float wy1 = yf - y0f;
        const float wx0 = 1.0f - wx1;
        const float wy0 = 1.0f - wy1;

        const int ix0 = (int)x0f;       // in [-1, 511]
        const int iy0 = (int)y0f;       // in [-1, 511]

        // x handling: entry xc holds texels (xc, xc+1). Right edge (ix1==512)
        // reads the zero-filled slot -> no mask needed. Left edge (ix0==-1):
        // clamp to entry 0, both lane groups read the FIRST half (texel 0),
        // and the wx0 group's weight is masked to 0.
        const bool xin = (ix0 >= 0);
        const int  xc  = xin ? ix0 : 0;
        const int  sel = chunk + (xin ? (xsel << 2) : 0);
        const float wxl = xsel ? wx1 : (xin ? wx0 : 0.f);

        // y handling: clamp + weight masking.
        const float w0 = ((iy0 >= 0)      ? wy0 : 0.f) * wxl;
        const float w1 = ((iy0 < RES - 1) ? wy1 : 0.f) * wxl;
        const int yc0 = (iy0 >= 0) ? iy0 : 0;
        const int yc1 = (iy0 < RES - 1) ? (iy0 + 1) : (RES - 1);

        const __half* base = g_P[p];
        const uint4 v0 = __ldg((const uint4*)(base + (yc0 * RES + xc) * PAIR_HALVES + sel * 8));
        const uint4 v1 = __ldg((const uint4*)(base + (yc1 * RES + xc) * PAIR_HALVES + sel * 8));

        const __half2* h0 = (const __half2*)&v0;
        const __half2* h1 = (const __half2*)&v1;
#pragma unroll
        for (int j = 0; j < 4; ++j) {
            const float2 f0 = __half22float2(h0[j]);
            const float2 f1 = __half22float2(h1[j]);
            acc[2 * j]     = fmaf(w0, f0.x, acc[2 * j]);
            acc[2 * j + 1] = fmaf(w0, f0.y, acc[2 * j + 1]);
            acc[2 * j]     = fmaf(w1, f1.x, acc[2 * j]);
            acc[2 * j + 1] = fmaf(w1, f1.y, acc[2 * j + 1]);
        }
    }

    // Combine the two x-corner partial sums (lane s <-> lane s^4, same chunk).
#pragma unroll
    for (int j = 0; j < 8; ++j)
        acc[j] += __shfl_xor_sync(0xffffffffu, acc[j], 4);

    // All 32 lanes store one float4: xsel=0 writes floats 0-3 of the chunk,
    // xsel=1 writes floats 4-7. Warp covers 512B contiguous.
    const float4 r = xsel ? make_float4(acc[4], acc[5], acc[6], acc[7])
                          : make_float4(acc[0], acc[1], acc[2], acc[3]);
    *(float4*)(out + pid * CH + chunk * 8 + xsel * 4) = r;
}

// ---------------------------------------------------------------------------
// kernel_launch
// inputs: xyz [N*3], T_xy, T_yz, T_zx [1*32*512*512] fp32 ; output [N*32] fp32
// ---------------------------------------------------------------------------
extern "C" void kernel_launch(void* const* d_in, const int* in_sizes, int n_in,
                              void* d_out, int out_size)
{
    const float* xyz  = (const float*)d_in[0];
    const float* t_xy = (const float*)d_in[1];
    const float* t_yz = (const float*)d_in[2];
    const float* t_zx = (const float*)d_in[3];
    float* out = (float*)d_out;

    const int npts = in_sizes[0] / 3;

    dim3 tgrid(RES, RES / 32, 3);
    dim3 tblock(32, 8);
    triplane_prep_kernel<<<tgrid, tblock>>>(t_xy, t_yz, t_zx);

    const long long total = (long long)npts * 8;
    const int block = 256;
    const int grid = (int)((total + block - 1) / block);
    triplane_sample_kernel<<<grid, block>>>(xyz, out, npts);
}

// round 6
// speedup vs baseline: 1.3373x; 1.3373x over previous
#include <cuda_runtime.h>
#include <cuda_fp16.h>
#include <stdint.h>

#define RES 512
#define CH 32
#define PLANE_ELEMS (RES * RES * CH)

// (H, W, C) transposed planes in fp16: each texel = 32 halves = 64 B.
// Texels (y,x) and (y,x+1) are ADJACENT -> both x corners in one 128B span.
__device__ __align__(128) __half g_TH[3][PLANE_ELEMS];

// ---------------------------------------------------------------------------
// Transpose (C, H, W) fp32 -> (H, W, C) fp16 via shared 32x32 tile.
// grid = (RES, RES/32, 3), block = (32, 8). Each thread loads 4 channels.
// ---------------------------------------------------------------------------
__global__ __launch_bounds__(256) void triplane_transpose_kernel(
    const float* __restrict__ t_xy,
    const float* __restrict__ t_yz,
    const float* __restrict__ t_zx)
{
    __shared__ float tile[32][33];   // [channel][x-in-tile]

    const int y  = blockIdx.x;
    const int x0 = blockIdx.y * 32;
    const int p  = blockIdx.z;
    const int tx = threadIdx.x;      // 0..31
    const int ty = threadIdx.y;      // 0..7

    const float* src = (p == 0) ? t_xy : (p == 1) ? t_yz : t_zx;
    const float* s = src + y * RES + x0 + tx;

#pragma unroll
    for (int i = 0; i < 4; ++i) {
        const int c = ty + 8 * i;
        tile[c][tx] = s[c * (RES * RES)];   // coalesced, MLP=4
    }
    __syncthreads();

    // Write 32 texels x 4 uint4-segments = 128 items; threads 0..127 do one each.
    const int tid = ty * 32 + tx;
    if (tid < 128) {
        const int xx  = tid >> 2;        // texel within tile (0..31)
        const int seg = tid & 3;         // which 16B segment of the 64B texel

        uint4 v;
#pragma unroll
        for (int j = 0; j < 4; ++j) {
            const int c = seg * 8 + 2 * j;
            ((__half2*)&v)[j] = __floats2half2_rn(tile[c][xx], tile[c + 1][xx]);
        }
        *(uint4*)(g_TH[p] + ((size_t)(y * RES + x0 + xx)) * CH + seg * 8) = v;
    }
}

// ---------------------------------------------------------------------------
// Sampling: 8 lanes per point. Lane s: xsel = s>>2 (x corner), chunk = s&3
// (8 channels). The 8 lanes of a point read a contiguous 128B span covering
// texels (y, ix0) and (y, ix0+1) -> 1-2 L1 wavefronts per (plane,row).
// ---------------------------------------------------------------------------
__global__ __launch_bounds__(256) void triplane_sample_kernel(
    const float* __restrict__ xyz,
    float* __restrict__ out,
    int npts)
{
    const int gtid  = blockIdx.x * blockDim.x + threadIdx.x;
    const int pid   = gtid >> 3;
    const int s     = gtid & 7;
    const int chunk = s & 3;
    const int xsel  = s >> 2;
    if (pid >= npts) return;

    const float cx = __ldg(xyz + pid * 3 + 0);
    const float cy = __ldg(xyz + pid * 3 + 1);
    const float cz = __ldg(xyz + pid * 3 + 2);

    // f_xy: (X, Y)   f_yz: (Y, Z)   f_zx: (Z, X)
    const float cA[3] = {cx, cy, cz};   // W coordinate
    const float cB[3] = {cy, cz, cx};   // H coordinate

    float acc[8];
#pragma unroll
    for (int j = 0; j < 8; ++j) acc[j] = 0.f;

#pragma unroll
    for (int p = 0; p < 3; ++p) {
        // pixel coord = 256*c + 255.5
        const float xf = fmaf(cA[p], 256.0f, 255.5f);
        const float yf = fmaf(cB[p], 256.0f, 255.5f);

        const float x0f = floorf(xf);
        const float y0f = floorf(yf);
        const float wx1 = xf - x0f;
        const float wy1 = yf - y0f;
        const float wx0 = 1.0f - wx1;
        const float wy0 = 1.0f - wy1;

        const int ix0 = (int)x0f;       // in [-1, 511]
        const int iy0 = (int)y0f;       // in [-1, 511]

        // This lane's x corner: clamp + weight-mask at the borders.
        const int  ix = ix0 + xsel;
        const bool vx = ((unsigned)ix < RES);
        const int  xc = vx ? ix : (ix < 0 ? 0 : RES - 1);
        const float wxl = vx ? (xsel ? wx1 : wx0) : 0.f;

        // y rows: clamp + weight-mask.
        const float w0 = ((iy0 >= 0)      ? wy0 : 0.f) * wxl;
        const float w1 = ((iy0 < RES - 1) ? wy1 : 0.f) * wxl;
        const int yc0 = (iy0 >= 0) ? iy0 : 0;
        const int yc1 = (iy0 < RES - 1) ? (iy0 + 1) : (RES - 1);

        const __half* base = g_TH[p] + chunk * 8;   // this lane's 8 channels
        const uint4 v0 = __ldg((const uint4*)(base + (yc0 * RES + xc) * CH));
        const uint4 v1 = __ldg((const uint4*)(base + (yc1 * RES + xc) * CH));

        const __half2* h0 = (const __half2*)&v0;
        const __half2* h1 = (const __half2*)&v1;
#pragma unroll
        for (int j = 0; j < 4; ++j) {
            const float2 f0 = __half22float2(h0[j]);
            const float2 f1 = __half22float2(h1[j]);
            acc[2 * j]     = fmaf(w0, f0.x, acc[2 * j]);
            acc[2 * j + 1] = fmaf(w0, f0.y, acc[2 * j + 1]);
            acc[2 * j]     = fmaf(w1, f1.x, acc[2 * j]);
            acc[2 * j + 1] = fmaf(w1, f1.y, acc[2 * j + 1]);
        }
    }

    // Combine the two x-corner partial sums (lane s <-> lane s^4, same chunk).
#pragma unroll
    for (int j = 0; j < 8; ++j)
        acc[j] += __shfl_xor_sync(0xffffffffu, acc[j], 4);

    // All 32 lanes store one float4: xsel=0 -> floats 0-3 of the chunk,
    // xsel=1 -> floats 4-7. Warp covers 512B contiguous.
    const float4 r = xsel ? make_float4(acc[4], acc[5], acc[6], acc[7])
                          : make_float4(acc[0], acc[1], acc[2], acc[3]);
    *(float4*)(out + pid * CH + chunk * 8 + xsel * 4) = r;
}

// ---------------------------------------------------------------------------
// kernel_launch
// inputs: xyz [N*3], T_xy, T_yz, T_zx [1*32*512*512] fp32 ; output [N*32] fp32
// ---------------------------------------------------------------------------
extern "C" void kernel_launch(void* const* d_in, const int* in_sizes, int n_in,
                              void* d_out, int out_size)
{
    const float* xyz  = (const float*)d_in[0];
    const float* t_xy = (const float*)d_in[1];
    const float* t_yz = (const float*)d_in[2];
    const float* t_zx = (const float*)d_in[3];
    float* out = (float*)d_out;

    const int npts = in_sizes[0] / 3;

    dim3 tgrid(RES, RES / 32, 3);
    dim3 tblock(32, 8);
    triplane_transpose_kernel<<<tgrid, tblock>>>(t_xy, t_yz, t_zx);

    const long long total = (long long)npts * 8;
    const int block = 256;
    const int grid = (int)((total + block - 1) / block);
    triplane_sample_kernel<<<grid, block>>>(xyz, out, npts);
}